// round 6
// baseline (speedup 1.0000x reference)
#include <cuda_runtime.h>
#include <mma.h>
#include <cstdint>

using namespace nvcuda;

#define MAXN 500000
#define MAXE 500000
#define F 128

// ---------------- scratch (static device globals; no allocation) ----------------
__device__ float g_h[(size_t)MAXN * F];   // h = x @ W
__device__ float g_s[MAXN];               // per-node dot with a_src
__device__ float g_d[MAXN];               // per-node dot with a_dst
__device__ float g_alpha[MAXE];           // per-edge exp(logit)
__device__ float g_sum;                   // softmax denominator

// ---------------- small helpers ----------------
__device__ __forceinline__ float warpSum(float v) {
    #pragma unroll
    for (int o = 16; o > 0; o >>= 1) v += __shfl_xor_sync(0xFFFFFFFFu, v, o);
    return v;
}

// ---------------- K1: h = x @ W, persistent pipelined wmma-tf32 ----------------
// grid ~ NUM_SM CTAs, 256 threads. Each CTA stages W (tf32) once, then loops over
// 128-row tiles with double-buffered cp.async x-tile staging.
// Separate paddings: A tile ld=132 (ld%32==4, conflict-free 8rx4c loads),
//                    B tile ld=144 (ld%32==16, conflict-free 2rx16c loads).
#define WLD 144
#define XLD 132
#define TILE_FLOATS (128 * XLD)
#define GSMEM_BYTES ((128 * WLD + 2 * TILE_FLOATS) * 4)   // 208,896 bytes

__device__ __forceinline__ uint32_t smem_u32(const void* p) {
    uint32_t a;
    asm("{ .reg .u64 t; cvta.to.shared.u64 t, %1; cvt.u32.u64 %0, t; }" : "=r"(a) : "l"(p));
    return a;
}

__device__ __forceinline__ void prefetch_tile(const float* __restrict__ x, int tile,
                                              float* dst, int tid) {
    const float4* src = reinterpret_cast<const float4*>(x + (size_t)tile * 128 * F);
    #pragma unroll
    for (int i = 0; i < 16; i++) {
        int q = tid + i * 256;
        int r = q >> 5;      // row 0..127
        int c4 = q & 31;     // float4 col
        uint32_t d = smem_u32(dst + r * XLD + c4 * 4);
        asm volatile("cp.async.cg.shared.global [%0], [%1], 16;" :: "r"(d), "l"(src + q) : "memory");
    }
    asm volatile("cp.async.commit_group;" ::: "memory");
}

__global__ __launch_bounds__(256) void gemm_mma_kernel(const float* __restrict__ x,
                                                       const float* __restrict__ w,
                                                       float* __restrict__ out,
                                                       int numTiles, int N) {
    extern __shared__ float smem[];
    float* sW = smem;                       // [128][WLD], tf32-converted
    float* sX0 = smem + 128 * WLD;
    float* sX1 = sX0 + TILE_FLOATS;
    const int tid = threadIdx.x;
    const int stride = gridDim.x;

    if (blockIdx.x == 0 && tid == 0) g_sum = 0.0f;

    // Zero `out` (fire-and-forget; drains behind compute, ordered by kernel end).
    {
        const float4 z = make_float4(0.f, 0.f, 0.f, 0.f);
        float4* o4 = reinterpret_cast<float4*>(out);
        size_t total = (size_t)N * 32;
        for (size_t i = (size_t)blockIdx.x * 256 + tid; i < total; i += (size_t)stride * 256)
            o4[i] = z;
    }

    // Stage W (K x N row-major) once, converting to tf32 (rna).
    #pragma unroll
    for (int i = 0; i < 16; i++) {
        int q = tid + i * 256;
        int k = q >> 5;
        int c4 = q & 31;
        float4 v = reinterpret_cast<const float4*>(w)[k * 32 + c4];
        v.x = wmma::__float_to_tf32(v.x);
        v.y = wmma::__float_to_tf32(v.y);
        v.z = wmma::__float_to_tf32(v.z);
        v.w = wmma::__float_to_tf32(v.w);
        *reinterpret_cast<float4*>(&sW[k * WLD + c4 * 4]) = v;
    }

    int t0 = blockIdx.x;
    if (t0 < numTiles) prefetch_tile(x, t0, sX0, tid);

    const int wid = tid >> 5;
    const int warp_m = wid & 3;          // 0..3
    const int warp_n = wid >> 2;         // 0..1
    const int n0 = warp_n * 64;

    int buf = 0;
    for (int t = t0; t < numTiles; t += stride) {
        asm volatile("cp.async.wait_group 0;" ::: "memory");
        __syncthreads();    // x tile ready; also covers W staging on first iter

        int tn = t + stride;
        if (tn < numTiles) prefetch_tile(x, tn, buf ? sX0 : sX1, tid);

        const float* cur = buf ? sX1 : sX0;
        const float* aBase = cur + warp_m * 32 * XLD;

        wmma::fragment<wmma::accumulator, 16, 16, 8, float> c[2][4];
        #pragma unroll
        for (int mi = 0; mi < 2; mi++)
            #pragma unroll
            for (int ni = 0; ni < 4; ni++) wmma::fill_fragment(c[mi][ni], 0.0f);

        #pragma unroll
        for (int kf = 0; kf < 16; kf++) {
            const int k = kf * 8;
            wmma::fragment<wmma::matrix_a, 16, 16, 8, wmma::precision::tf32, wmma::row_major> a[2];
            wmma::fragment<wmma::matrix_b, 16, 16, 8, wmma::precision::tf32, wmma::row_major> b[4];
            #pragma unroll
            for (int mi = 0; mi < 2; mi++) {
                wmma::load_matrix_sync(a[mi], aBase + mi * 16 * XLD + k, XLD);
                #pragma unroll
                for (int e = 0; e < a[mi].num_elements; e++)
                    a[mi].x[e] = wmma::__float_to_tf32(a[mi].x[e]);
            }
            #pragma unroll
            for (int ni = 0; ni < 4; ni++)
                wmma::load_matrix_sync(b[ni], &sW[k * WLD + n0 + ni * 16], WLD);
            #pragma unroll
            for (int mi = 0; mi < 2; mi++)
                #pragma unroll
                for (int ni = 0; ni < 4; ni++)
                    wmma::mma_sync(c[mi][ni], a[mi], b[ni], c[mi][ni]);
        }

        const size_t m0 = (size_t)t * 128 + warp_m * 32;
        #pragma unroll
        for (int mi = 0; mi < 2; mi++)
            #pragma unroll
            for (int ni = 0; ni < 4; ni++)
                wmma::store_matrix_sync(&g_h[(m0 + mi * 16) * F + n0 + ni * 16],
                                        c[mi][ni], F, wmma::mem_row_major);
        buf ^= 1;
    }
}

// Tail rows [M0, N): one CTA per row, 128 threads (one per output col). Exact fp32.
__global__ __launch_bounds__(128) void gemm_tail_kernel(const float* __restrict__ x,
                                                        const float* __restrict__ w,
                                                        int M0, int N) {
    __shared__ float sx[F];
    int r = M0 + blockIdx.x;
    if (r >= N) return;
    sx[threadIdx.x] = x[(size_t)r * F + threadIdx.x];
    __syncthreads();
    float acc = 0.f;
    #pragma unroll 8
    for (int k = 0; k < F; k++) acc = fmaf(sx[k], w[k * F + threadIdx.x], acc);
    g_h[(size_t)r * F + threadIdx.x] = acc;
}

// ---------------- K2: out[row[e]] += h[col[e]]  (one warp per edge) ----------------
__global__ __launch_bounds__(256) void scatter_kernel(const int* __restrict__ ei,
                                                      float* __restrict__ out, int E) {
    int e = (blockIdx.x * blockDim.x + threadIdx.x) >> 5;
    int lane = threadIdx.x & 31;
    if (e >= E) return;
    int r = ei[e];
    int c = ei[E + e];
    float4 v = reinterpret_cast<const float4*>(&g_h[(size_t)c * F])[lane];
    float* dst = out + (size_t)r * F + lane * 4;
    asm volatile("red.global.add.v4.f32 [%0], {%1,%2,%3,%4};"
                 :: "l"(dst), "f"(v.x), "f"(v.y), "f"(v.z), "f"(v.w)
                 : "memory");
}

// ---------------- K3: s[i], d[i] from relu(out+bias) — READ ONLY on out ----------------
__global__ __launch_bounds__(256) void postproc_kernel(const float* __restrict__ out,
                                                       const float* __restrict__ bias,
                                                       const float* __restrict__ att,
                                                       int N) {
    int node = (blockIdx.x * blockDim.x + threadIdx.x) >> 5;
    int lane = threadIdx.x & 31;
    if (node >= N) return;
    float4 v = reinterpret_cast<const float4*>(out + (size_t)node * F)[lane];
    float4 b = reinterpret_cast<const float4*>(bias)[lane];
    v.x = fmaxf(v.x + b.x, 0.f);
    v.y = fmaxf(v.y + b.y, 0.f);
    v.z = fmaxf(v.z + b.z, 0.f);
    v.w = fmaxf(v.w + b.w, 0.f);
    float4 as = reinterpret_cast<const float4*>(att)[lane];       // a_src
    float4 ad = reinterpret_cast<const float4*>(att)[32 + lane];  // a_dst
    float ss = v.x * as.x + v.y * as.y + v.z * as.z + v.w * as.w;
    float dd = v.x * ad.x + v.y * ad.y + v.z * ad.z + v.w * ad.w;
    ss = warpSum(ss);
    dd = warpSum(dd);
    if (lane == 0) { g_s[node] = ss; g_d[node] = dd; }
}

// ---------------- K4: alpha[e]=exp(leaky_relu(s[row]+d[col])); global sum ----------
// Unstable softmax (no max subtraction): logits are small dot products, |logit| << 88,
// so exp cannot overflow; result is mathematically identical to max-shifted softmax.
__global__ __launch_bounds__(256) void alpha_exp_kernel(const int* __restrict__ ei, int E) {
    int e = blockIdx.x * blockDim.x + threadIdx.x;
    int lane = threadIdx.x & 31;
    int wid = threadIdx.x >> 5;
    float ev = 0.f;
    if (e < E) {
        int r = ei[e];
        int c = ei[E + e];
        float v = g_s[r] + g_d[c];
        v = (v > 0.f) ? v : 0.2f * v;
        ev = __expf(v);
        g_alpha[e] = ev;
    }
    __shared__ float ssum[8];
    float s = warpSum(ev);
    if (lane == 0) ssum[wid] = s;
    __syncthreads();
    if (wid == 0) {
        float t = (lane < 8) ? ssum[lane] : 0.f;
        t = warpSum(t);
        if (lane == 0) atomicAdd(&g_sum, t);
    }
}

// ---------------- K5: out[i,:] = relu(out[i,:]+bias) * alpha[i]/sum (in place) -------
__global__ __launch_bounds__(256) void scale_kernel(float* __restrict__ out,
                                                    const float* __restrict__ bias,
                                                    int N) {
    size_t i = (size_t)blockIdx.x * blockDim.x + threadIdx.x;  // float4 index
    if (i >= (size_t)N * 32) return;
    int node = (int)(i >> 5);
    float sc = g_alpha[node] / g_sum;
    float4 v = reinterpret_cast<float4*>(out)[i];
    float4 b = reinterpret_cast<const float4*>(bias)[i & 31];
    v.x = fmaxf(v.x + b.x, 0.f) * sc;
    v.y = fmaxf(v.y + b.y, 0.f) * sc;
    v.z = fmaxf(v.z + b.z, 0.f) * sc;
    v.w = fmaxf(v.w + b.w, 0.f) * sc;
    reinterpret_cast<float4*>(out)[i] = v;
}

extern "C" void kernel_launch(void* const* d_in, const int* in_sizes, int n_in,
                              void* d_out, int out_size) {
    const float* x   = (const float*)d_in[0];
    const int* ei    = (const int*)d_in[1];     // edge_index: int32
    const float* w   = (const float*)d_in[2];
    const float* att = (const float*)d_in[3];
    const float* bias= (const float*)d_in[4];
    float* out       = (float*)d_out;

    int N = in_sizes[0] / F;   // 500000
    int E = in_sizes[1] / 2;   // 500000

    static int smem_set = 0;
    if (!smem_set) {
        cudaFuncSetAttribute(gemm_mma_kernel, cudaFuncAttributeMaxDynamicSharedMemorySize, GSMEM_BYTES);
        smem_set = 1;
    }

    int fullTiles = N / 128;           // 3906
    int M0 = fullTiles * 128;          // 499968
    int tailRows = N - M0;             // 32
    int gemmGrid = 152;                // GB300: 152 SMs
    if (gemmGrid > fullTiles) gemmGrid = fullTiles;

    gemm_mma_kernel<<<gemmGrid, 256, GSMEM_BYTES>>>(x, w, out, fullTiles, N);
    if (tailRows > 0) gemm_tail_kernel<<<tailRows, 128>>>(x, w, M0, N);
    scatter_kernel<<<(E + 7) / 8, 256>>>(ei, out, E);
    postproc_kernel<<<(N + 7) / 8, 256>>>(out, bias, att, N);
    alpha_exp_kernel<<<(E + 255) / 256, 256>>>(ei, E);
    scale_kernel<<<(int)(((size_t)N * 32 + 255) / 256), 256>>>(out, bias, N);
}

// round 7
// speedup vs baseline: 1.2522x; 1.2522x over previous
#include <cuda_runtime.h>
#include <cuda_fp16.h>
#include <mma.h>
#include <cstdint>

using namespace nvcuda;

#define MAXN 500000
#define MAXE 500000
#define F 128

// ---------------- scratch (static device globals; no allocation) ----------------
__device__ float g_h[(size_t)MAXN * F];     // h = x @ W (fp32)
__device__ __half g_xh[(size_t)MAXN * F];   // x in fp16
__device__ float g_s[MAXN];                 // per-node dot with a_src
__device__ float g_d[MAXN];                 // per-node dot with a_dst
__device__ float g_alpha[MAXE];             // per-edge exp(logit)
__device__ float g_sum;                     // softmax denominator

// ---------------- small helpers ----------------
__device__ __forceinline__ float warpSum(float v) {
    #pragma unroll
    for (int o = 16; o > 0; o >>= 1) v += __shfl_xor_sync(0xFFFFFFFFu, v, o);
    return v;
}
__device__ __forceinline__ uint32_t smem_u32(const void* p) {
    uint32_t a;
    asm("{ .reg .u64 t; cvta.to.shared.u64 t, %1; cvt.u32.u64 %0, t; }" : "=r"(a) : "l"(p));
    return a;
}

// ---------------- K0: xh = fp16(x); out = 0; g_sum = 0 ----------------
__global__ __launch_bounds__(256) void convert_zero_kernel(const float* __restrict__ x,
                                                           float* __restrict__ out,
                                                           size_t total4) {
    size_t i = (size_t)blockIdx.x * blockDim.x + threadIdx.x;   // float4 index
    if (i == 0) g_sum = 0.0f;
    if (i >= total4) return;
    float4 v = reinterpret_cast<const float4*>(x)[i];
    __half2 p0 = __floats2half2_rn(v.x, v.y);
    __half2 p1 = __floats2half2_rn(v.z, v.w);
    uint2 pk;
    pk.x = *reinterpret_cast<uint32_t*>(&p0);
    pk.y = *reinterpret_cast<uint32_t*>(&p1);
    reinterpret_cast<uint2*>(g_xh)[i] = pk;
    reinterpret_cast<float4*>(out)[i] = make_float4(0.f, 0.f, 0.f, 0.f);
}

// ---------------- K1: h = x @ W, persistent pipelined wmma-fp16 ----------------
// 256 threads, 8 warps = 4(M) x 2(N); warp tile 32x64 = 2x4 m16n16k16 frags.
// W (fp16) staged once per CTA; x tiles (fp16) double-buffered via cp.async.
// Row pad 136 halfs (272B): 8x8 ldmatrix rows spread over all 32 banks.
#define WH_LD 136
#define XH_LD 136
#define XTILE_HALFS (128 * XH_LD)
#define GSMEM_BYTES ((128 * WH_LD + 2 * XTILE_HALFS) * 2)   // 104,448 bytes

__device__ __forceinline__ void prefetch_tile16(int tile, __half* dst, int tid) {
    const __half* src = g_xh + (size_t)tile * 128 * F;
    #pragma unroll
    for (int i = 0; i < 8; i++) {
        int q = tid + i * 256;          // 16B chunk id, 2048 total
        int r = q >> 4;                 // row 0..127
        int c16 = q & 15;               // 16B unit (8 halfs)
        uint32_t d = smem_u32(dst + r * XH_LD + c16 * 8);
        asm volatile("cp.async.cg.shared.global [%0], [%1], 16;"
                     :: "r"(d), "l"(src + r * F + c16 * 8) : "memory");
    }
    asm volatile("cp.async.commit_group;" ::: "memory");
}

__global__ __launch_bounds__(256) void gemm_mma_kernel(const float* __restrict__ w,
                                                       int numTiles) {
    extern __shared__ __half smem_h[];
    __half* sW = smem_h;                      // [128][WH_LD]
    __half* sX0 = smem_h + 128 * WH_LD;
    __half* sX1 = sX0 + XTILE_HALFS;
    const int tid = threadIdx.x;
    const int stride = gridDim.x;

    // Stage W (K x N row-major) once as fp16.
    #pragma unroll
    for (int i = 0; i < 16; i++) {
        int q = tid + i * 256;       // float4 id, 4096 total
        int k = q >> 5;
        int c4 = q & 31;
        float4 v = reinterpret_cast<const float4*>(w)[q];
        __half2 p0 = __floats2half2_rn(v.x, v.y);
        __half2 p1 = __floats2half2_rn(v.z, v.w);
        *reinterpret_cast<__half2*>(&sW[k * WH_LD + c4 * 4])     = p0;
        *reinterpret_cast<__half2*>(&sW[k * WH_LD + c4 * 4 + 2]) = p1;
    }

    int t0 = blockIdx.x;
    if (t0 < numTiles) prefetch_tile16(t0, sX0, tid);

    const int wid = tid >> 5;
    const int warp_m = wid & 3;          // 0..3
    const int warp_n = wid >> 2;         // 0..1
    const int n0 = warp_n * 64;

    int buf = 0;
    for (int t = t0; t < numTiles; t += stride) {
        asm volatile("cp.async.wait_group 0;" ::: "memory");
        __syncthreads();    // x tile ready; also covers W staging on first iter

        int tn = t + stride;
        if (tn < numTiles) prefetch_tile16(tn, buf ? sX0 : sX1, tid);

        const __half* cur = buf ? sX1 : sX0;
        const __half* aBase = cur + warp_m * 32 * XH_LD;

        wmma::fragment<wmma::accumulator, 16, 16, 16, float> c[2][4];
        #pragma unroll
        for (int mi = 0; mi < 2; mi++)
            #pragma unroll
            for (int ni = 0; ni < 4; ni++) wmma::fill_fragment(c[mi][ni], 0.0f);

        #pragma unroll
        for (int kf = 0; kf < 8; kf++) {
            const int k = kf * 16;
            wmma::fragment<wmma::matrix_a, 16, 16, 16, __half, wmma::row_major> a[2];
            wmma::fragment<wmma::matrix_b, 16, 16, 16, __half, wmma::row_major> b[4];
            #pragma unroll
            for (int mi = 0; mi < 2; mi++)
                wmma::load_matrix_sync(a[mi], aBase + mi * 16 * XH_LD + k, XH_LD);
            #pragma unroll
            for (int ni = 0; ni < 4; ni++)
                wmma::load_matrix_sync(b[ni], &sW[k * WH_LD + n0 + ni * 16], WH_LD);
            #pragma unroll
            for (int mi = 0; mi < 2; mi++)
                #pragma unroll
                for (int ni = 0; ni < 4; ni++)
                    wmma::mma_sync(c[mi][ni], a[mi], b[ni], c[mi][ni]);
        }

        const size_t m0 = (size_t)t * 128 + warp_m * 32;
        #pragma unroll
        for (int mi = 0; mi < 2; mi++)
            #pragma unroll
            for (int ni = 0; ni < 4; ni++)
                wmma::store_matrix_sync(&g_h[(m0 + mi * 16) * F + n0 + ni * 16],
                                        c[mi][ni], F, wmma::mem_row_major);
        buf ^= 1;
    }
}

// Tail rows [M0, N): one CTA per row, 128 threads (one per output col). Exact fp32.
__global__ __launch_bounds__(128) void gemm_tail_kernel(const float* __restrict__ x,
                                                        const float* __restrict__ w,
                                                        int M0, int N) {
    __shared__ float sx[F];
    int r = M0 + blockIdx.x;
    if (r >= N) return;
    sx[threadIdx.x] = x[(size_t)r * F + threadIdx.x];
    __syncthreads();
    float acc = 0.f;
    #pragma unroll 8
    for (int k = 0; k < F; k++) acc = fmaf(sx[k], w[k * F + threadIdx.x], acc);
    g_h[(size_t)r * F + threadIdx.x] = acc;
}

// ---------------- K2: out[row[e]] += h[col[e]]  (one warp per edge) ----------------
__global__ __launch_bounds__(256) void scatter_kernel(const int* __restrict__ ei,
                                                      float* __restrict__ out, int E) {
    int e = (blockIdx.x * blockDim.x + threadIdx.x) >> 5;
    int lane = threadIdx.x & 31;
    if (e >= E) return;
    int r = ei[e];
    int c = ei[E + e];
    float4 v = reinterpret_cast<const float4*>(&g_h[(size_t)c * F])[lane];
    float* dst = out + (size_t)r * F + lane * 4;
    asm volatile("red.global.add.v4.f32 [%0], {%1,%2,%3,%4};"
                 :: "l"(dst), "f"(v.x), "f"(v.y), "f"(v.z), "f"(v.w)
                 : "memory");
}

// ---------------- K3: s[i], d[i] from relu(out+bias) — READ ONLY on out ----------------
__global__ __launch_bounds__(256) void postproc_kernel(const float* __restrict__ out,
                                                       const float* __restrict__ bias,
                                                       const float* __restrict__ att,
                                                       int N) {
    int node = (blockIdx.x * blockDim.x + threadIdx.x) >> 5;
    int lane = threadIdx.x & 31;
    if (node >= N) return;
    float4 v = reinterpret_cast<const float4*>(out + (size_t)node * F)[lane];
    float4 b = reinterpret_cast<const float4*>(bias)[lane];
    v.x = fmaxf(v.x + b.x, 0.f);
    v.y = fmaxf(v.y + b.y, 0.f);
    v.z = fmaxf(v.z + b.z, 0.f);
    v.w = fmaxf(v.w + b.w, 0.f);
    float4 as = reinterpret_cast<const float4*>(att)[lane];       // a_src
    float4 ad = reinterpret_cast<const float4*>(att)[32 + lane];  // a_dst
    float ss = v.x * as.x + v.y * as.y + v.z * as.z + v.w * as.w;
    float dd = v.x * ad.x + v.y * ad.y + v.z * ad.z + v.w * ad.w;
    ss = warpSum(ss);
    dd = warpSum(dd);
    if (lane == 0) { g_s[node] = ss; g_d[node] = dd; }
}

// ---------------- K4: alpha[e]=exp(leaky_relu(s[row]+d[col])); global sum ----------
// Unstable softmax (no max subtraction): logits are small dot products, |logit| << 88,
// so exp cannot overflow; result is mathematically identical to max-shifted softmax.
__global__ __launch_bounds__(256) void alpha_exp_kernel(const int* __restrict__ ei, int E) {
    int e = blockIdx.x * blockDim.x + threadIdx.x;
    int lane = threadIdx.x & 31;
    int wid = threadIdx.x >> 5;
    float ev = 0.f;
    if (e < E) {
        int r = ei[e];
        int c = ei[E + e];
        float v = g_s[r] + g_d[c];
        v = (v > 0.f) ? v : 0.2f * v;
        ev = __expf(v);
        g_alpha[e] = ev;
    }
    __shared__ float ssum[8];
    float s = warpSum(ev);
    if (lane == 0) ssum[wid] = s;
    __syncthreads();
    if (wid == 0) {
        float t = (lane < 8) ? ssum[lane] : 0.f;
        t = warpSum(t);
        if (lane == 0) atomicAdd(&g_sum, t);
    }
}

// ---------------- K5: out[i,:] = relu(out[i,:]+bias) * alpha[i]/sum (in place) -------
__global__ __launch_bounds__(256) void scale_kernel(float* __restrict__ out,
                                                    const float* __restrict__ bias,
                                                    int N) {
    size_t i = (size_t)blockIdx.x * blockDim.x + threadIdx.x;  // float4 index
    if (i >= (size_t)N * 32) return;
    int node = (int)(i >> 5);
    float sc = g_alpha[node] / g_sum;
    float4 v = reinterpret_cast<float4*>(out)[i];
    float4 b = reinterpret_cast<const float4*>(bias)[i & 31];
    v.x = fmaxf(v.x + b.x, 0.f) * sc;
    v.y = fmaxf(v.y + b.y, 0.f) * sc;
    v.z = fmaxf(v.z + b.z, 0.f) * sc;
    v.w = fmaxf(v.w + b.w, 0.f) * sc;
    reinterpret_cast<float4*>(out)[i] = v;
}

extern "C" void kernel_launch(void* const* d_in, const int* in_sizes, int n_in,
                              void* d_out, int out_size) {
    const float* x   = (const float*)d_in[0];
    const int* ei    = (const int*)d_in[1];     // edge_index: int32
    const float* w   = (const float*)d_in[2];
    const float* att = (const float*)d_in[3];
    const float* bias= (const float*)d_in[4];
    float* out       = (float*)d_out;

    int N = in_sizes[0] / F;   // 500000
    int E = in_sizes[1] / 2;   // 500000

    static int smem_set = 0;
    if (!smem_set) {
        cudaFuncSetAttribute(gemm_mma_kernel, cudaFuncAttributeMaxDynamicSharedMemorySize, GSMEM_BYTES);
        smem_set = 1;
    }

    int fullTiles = N / 128;           // 3906
    int M0 = fullTiles * 128;          // 499968
    int tailRows = N - M0;             // 32
    int gemmGrid = 304;                // 2 CTAs/SM on 152 SMs
    if (gemmGrid > fullTiles) gemmGrid = fullTiles;

    size_t total4 = (size_t)N * 32;    // float4 count of x / out
    convert_zero_kernel<<<(int)((total4 + 255) / 256), 256>>>(x, out, total4);
    gemm_mma_kernel<<<gemmGrid, 256, GSMEM_BYTES>>>(w, fullTiles);
    if (tailRows > 0) gemm_tail_kernel<<<tailRows, 128>>>(x, w, M0, N);
    scatter_kernel<<<(E + 7) / 8, 256>>>(ei, out, E);
    postproc_kernel<<<(N + 7) / 8, 256>>>(out, bias, att, N);
    alpha_exp_kernel<<<(E + 255) / 256, 256>>>(ei, E);
    scale_kernel<<<(int)(((size_t)N * 32 + 255) / 256), 256>>>(out, bias, N);
}

// round 8
// speedup vs baseline: 1.3757x; 1.0986x over previous
#include <cuda_runtime.h>
#include <cuda_fp16.h>
#include <mma.h>
#include <cstdint>

using namespace nvcuda;

#define MAXN 500000
#define MAXE 500000
#define F 128

// ---------------- scratch (static device globals; no allocation) ----------------
__device__ __half g_h[(size_t)MAXN * F];    // h = x @ W (fp16)
__device__ float g_s[MAXN];                 // per-node dot with a_src
__device__ float g_d[MAXN];                 // per-node dot with a_dst
__device__ float g_alpha[MAXE];             // per-edge exp(logit)
__device__ float g_sum;                     // softmax denominator

// ---------------- small helpers ----------------
__device__ __forceinline__ float warpSum(float v) {
    #pragma unroll
    for (int o = 16; o > 0; o >>= 1) v += __shfl_xor_sync(0xFFFFFFFFu, v, o);
    return v;
}
__device__ __forceinline__ uint32_t smem_u32(const void* p) {
    uint32_t a;
    asm("{ .reg .u64 t; cvta.to.shared.u64 t, %1; cvt.u32.u64 %0, t; }" : "=r"(a) : "l"(p));
    return a;
}

// ---------------- K1: h = x @ W, persistent pipelined wmma-fp16 ----------------
// 256 threads, 8 warps = 4(M) x 2(N); warp tile 32x64 = 2x4 m16n16k16 frags.
// x staged fp32 via cp.async, converted to fp16 in SMEM each tile.
// SMEM bytes: W 34816 | xf32 65536 | xh16 34816 | staging 65536 = 200704.
#define WH_LD 136
#define XH_LD 136
#define SW_HALFS   (128 * WH_LD)              // 17408
#define XF_FLOATS  (128 * 128)                // 16384
#define XH_HALFS   (128 * XH_LD)              // 17408
#define STG_FLOATS (8 * 32 * 64)              // 16384
#define GSMEM_BYTES (SW_HALFS * 2 + XF_FLOATS * 4 + XH_HALFS * 2 + STG_FLOATS * 4)

__device__ __forceinline__ void prefetch_tile32(const float* __restrict__ x, int tile,
                                                float* dst, int tid) {
    const float4* src = reinterpret_cast<const float4*>(x + (size_t)tile * 128 * F);
    #pragma unroll
    for (int i = 0; i < 16; i++) {
        int q = tid + i * 256;               // float4 id, 4096 total
        uint32_t d = smem_u32(dst + q * 4);
        asm volatile("cp.async.cg.shared.global [%0], [%1], 16;"
                     :: "r"(d), "l"(src + q) : "memory");
    }
    asm volatile("cp.async.commit_group;" ::: "memory");
}

__global__ __launch_bounds__(256) void gemm_mma_kernel(const float* __restrict__ x,
                                                       const float* __restrict__ w,
                                                       int numTiles) {
    extern __shared__ char smem_raw[];
    __half* sW  = reinterpret_cast<__half*>(smem_raw);
    float*  sXf = reinterpret_cast<float*>(smem_raw + SW_HALFS * 2);
    __half* sXh = reinterpret_cast<__half*>(smem_raw + SW_HALFS * 2 + XF_FLOATS * 4);
    float*  sStg = reinterpret_cast<float*>(smem_raw + SW_HALFS * 2 + XF_FLOATS * 4 + XH_HALFS * 2);
    const int tid = threadIdx.x;
    const int stride = gridDim.x;

    if (blockIdx.x == 0 && tid == 0) g_sum = 0.0f;

    // Stage W (K x N row-major) once as fp16.
    #pragma unroll
    for (int i = 0; i < 16; i++) {
        int q = tid + i * 256;       // float4 id, 4096 total
        int k = q >> 5;
        int c4 = q & 31;
        float4 v = reinterpret_cast<const float4*>(w)[q];
        __half2 p0 = __floats2half2_rn(v.x, v.y);
        __half2 p1 = __floats2half2_rn(v.z, v.w);
        *reinterpret_cast<__half2*>(&sW[k * WH_LD + c4 * 4])     = p0;
        *reinterpret_cast<__half2*>(&sW[k * WH_LD + c4 * 4 + 2]) = p1;
    }

    int t0 = blockIdx.x;
    if (t0 < numTiles) prefetch_tile32(x, t0, sXf, tid);

    const int wid = tid >> 5;
    const int lane = tid & 31;
    const int warp_m = wid & 3;          // 0..3
    const int warp_n = wid >> 2;         // 0..1
    const int n0 = warp_n * 64;
    float* myStg = sStg + wid * 2048;    // 32x64 fp32 per warp

    for (int t = t0; t < numTiles; t += stride) {
        asm volatile("cp.async.wait_group 0;" ::: "memory");
        __syncthreads();    // x fp32 tile ready; also covers W staging on first iter

        // Convert fp32 tile -> fp16 tile (padded ld).
        #pragma unroll
        for (int i = 0; i < 16; i++) {
            int q = tid + i * 256;       // float4 id
            int r = q >> 5;
            int c4 = q & 31;
            float4 v = *reinterpret_cast<const float4*>(&sXf[q * 4]);
            __half2 p0 = __floats2half2_rn(v.x, v.y);
            __half2 p1 = __floats2half2_rn(v.z, v.w);
            *reinterpret_cast<__half2*>(&sXh[r * XH_LD + c4 * 4])     = p0;
            *reinterpret_cast<__half2*>(&sXh[r * XH_LD + c4 * 4 + 2]) = p1;
        }
        __syncthreads();

        int tn = t + stride;
        if (tn < numTiles) prefetch_tile32(x, tn, sXf, tid);

        const __half* aBase = sXh + warp_m * 32 * XH_LD;

        wmma::fragment<wmma::accumulator, 16, 16, 16, float> c[2][4];
        #pragma unroll
        for (int mi = 0; mi < 2; mi++)
            #pragma unroll
            for (int ni = 0; ni < 4; ni++) wmma::fill_fragment(c[mi][ni], 0.0f);

        #pragma unroll
        for (int kf = 0; kf < 8; kf++) {
            const int k = kf * 16;
            wmma::fragment<wmma::matrix_a, 16, 16, 16, __half, wmma::row_major> a[2];
            wmma::fragment<wmma::matrix_b, 16, 16, 16, __half, wmma::row_major> b[4];
            #pragma unroll
            for (int mi = 0; mi < 2; mi++)
                wmma::load_matrix_sync(a[mi], aBase + mi * 16 * XH_LD + k, XH_LD);
            #pragma unroll
            for (int ni = 0; ni < 4; ni++)
                wmma::load_matrix_sync(b[ni], &sW[k * WH_LD + n0 + ni * 16], WH_LD);
            #pragma unroll
            for (int mi = 0; mi < 2; mi++)
                #pragma unroll
                for (int ni = 0; ni < 4; ni++)
                    wmma::mma_sync(c[mi][ni], a[mi], b[ni], c[mi][ni]);
        }

        // Epilogue: frags -> per-warp smem staging (fp32) -> fp16 global.
        #pragma unroll
        for (int mi = 0; mi < 2; mi++)
            #pragma unroll
            for (int ni = 0; ni < 4; ni++)
                wmma::store_matrix_sync(myStg + mi * 16 * 64 + ni * 16,
                                        c[mi][ni], 64, wmma::mem_row_major);
        __syncwarp();
        {
            const size_t m0 = (size_t)t * 128 + warp_m * 32;
            const float2* stg2 = reinterpret_cast<const float2*>(myStg);
            #pragma unroll 4
            for (int r = 0; r < 32; r++) {
                float2 v = stg2[r * 32 + lane];
                __half2 h2 = __floats2half2_rn(v.x, v.y);
                *reinterpret_cast<__half2*>(&g_h[(m0 + r) * F + n0 + lane * 2]) = h2;
            }
        }
        __syncwarp();
    }
}

// Tail rows [M0, N): one CTA per row, 128 threads (one per output col). fp32 math.
__global__ __launch_bounds__(128) void gemm_tail_kernel(const float* __restrict__ x,
                                                        const float* __restrict__ w,
                                                        int M0, int N) {
    __shared__ float sx[F];
    int r = M0 + blockIdx.x;
    if (r >= N) return;
    sx[threadIdx.x] = x[(size_t)r * F + threadIdx.x];
    __syncthreads();
    float acc = 0.f;
    #pragma unroll 8
    for (int k = 0; k < F; k++) acc = fmaf(sx[k], w[k * F + threadIdx.x], acc);
    g_h[(size_t)r * F + threadIdx.x] = __float2half_rn(acc);
}

// ---------------- K2: out[row[e]] += h[col[e]]  (one warp per edge, fp16 gather) ----
__global__ __launch_bounds__(256) void scatter_kernel(const int* __restrict__ ei,
                                                      float* __restrict__ out, int E) {
    int e = (blockIdx.x * blockDim.x + threadIdx.x) >> 5;
    int lane = threadIdx.x & 31;
    if (e >= E) return;
    int r = ei[e];
    int c = ei[E + e];
    uint2 pk = reinterpret_cast<const uint2*>(&g_h[(size_t)c * F])[lane];  // 4 halfs
    __half2 h0 = *reinterpret_cast<__half2*>(&pk.x);
    __half2 h1 = *reinterpret_cast<__half2*>(&pk.y);
    float2 f0 = __half22float2(h0);
    float2 f1 = __half22float2(h1);
    float* dst = out + (size_t)r * F + lane * 4;
    asm volatile("red.global.add.v4.f32 [%0], {%1,%2,%3,%4};"
                 :: "l"(dst), "f"(f0.x), "f"(f0.y), "f"(f1.x), "f"(f1.y)
                 : "memory");
}

// ---------------- K3: s[i], d[i] from relu(out+bias) — READ ONLY on out ----------------
__global__ __launch_bounds__(256) void postproc_kernel(const float* __restrict__ out,
                                                       const float* __restrict__ bias,
                                                       const float* __restrict__ att,
                                                       int N) {
    int node = (blockIdx.x * blockDim.x + threadIdx.x) >> 5;
    int lane = threadIdx.x & 31;
    if (node >= N) return;
    float4 v = reinterpret_cast<const float4*>(out + (size_t)node * F)[lane];
    float4 b = reinterpret_cast<const float4*>(bias)[lane];
    v.x = fmaxf(v.x + b.x, 0.f);
    v.y = fmaxf(v.y + b.y, 0.f);
    v.z = fmaxf(v.z + b.z, 0.f);
    v.w = fmaxf(v.w + b.w, 0.f);
    float4 as = reinterpret_cast<const float4*>(att)[lane];       // a_src
    float4 ad = reinterpret_cast<const float4*>(att)[32 + lane];  // a_dst
    float ss = v.x * as.x + v.y * as.y + v.z * as.z + v.w * as.w;
    float dd = v.x * ad.x + v.y * ad.y + v.z * ad.z + v.w * ad.w;
    ss = warpSum(ss);
    dd = warpSum(dd);
    if (lane == 0) { g_s[node] = ss; g_d[node] = dd; }
}

// ---------------- K4: alpha[e]=exp(leaky_relu(s[row]+d[col])); global sum ----------
// Unstable softmax (no max subtraction): logits are small dot products, |logit| << 88,
// so exp cannot overflow; result is mathematically identical to max-shifted softmax.
__global__ __launch_bounds__(256) void alpha_exp_kernel(const int* __restrict__ ei, int E) {
    int e = blockIdx.x * blockDim.x + threadIdx.x;
    int lane = threadIdx.x & 31;
    int wid = threadIdx.x >> 5;
    float ev = 0.f;
    if (e < E) {
        int r = ei[e];
        int c = ei[E + e];
        float v = g_s[r] + g_d[c];
        v = (v > 0.f) ? v : 0.2f * v;
        ev = __expf(v);
        g_alpha[e] = ev;
    }
    __shared__ float ssum[8];
    float s = warpSum(ev);
    if (lane == 0) ssum[wid] = s;
    __syncthreads();
    if (wid == 0) {
        float t = (lane < 8) ? ssum[lane] : 0.f;
        t = warpSum(t);
        if (lane == 0) atomicAdd(&g_sum, t);
    }
}

// ---------------- K5: out[i,:] = relu(out[i,:]+bias) * alpha[i]/sum (in place) -------
__global__ __launch_bounds__(256) void scale_kernel(float* __restrict__ out,
                                                    const float* __restrict__ bias,
                                                    int N) {
    size_t i = (size_t)blockIdx.x * blockDim.x + threadIdx.x;  // float4 index
    if (i >= (size_t)N * 32) return;
    int node = (int)(i >> 5);
    float sc = g_alpha[node] / g_sum;
    float4 v = reinterpret_cast<float4*>(out)[i];
    float4 b = reinterpret_cast<const float4*>(bias)[i & 31];
    v.x = fmaxf(v.x + b.x, 0.f) * sc;
    v.y = fmaxf(v.y + b.y, 0.f) * sc;
    v.z = fmaxf(v.z + b.z, 0.f) * sc;
    v.w = fmaxf(v.w + b.w, 0.f) * sc;
    reinterpret_cast<float4*>(out)[i] = v;
}

extern "C" void kernel_launch(void* const* d_in, const int* in_sizes, int n_in,
                              void* d_out, int out_size) {
    const float* x   = (const float*)d_in[0];
    const int* ei    = (const int*)d_in[1];     // edge_index: int32
    const float* w   = (const float*)d_in[2];
    const float* att = (const float*)d_in[3];
    const float* bias= (const float*)d_in[4];
    float* out       = (float*)d_out;

    int N = in_sizes[0] / F;   // 500000
    int E = in_sizes[1] / 2;   // 500000

    static int smem_set = 0;
    if (!smem_set) {
        cudaFuncSetAttribute(gemm_mma_kernel, cudaFuncAttributeMaxDynamicSharedMemorySize, GSMEM_BYTES);
        smem_set = 1;
    }

    int fullTiles = N / 128;           // 3906
    int M0 = fullTiles * 128;          // 499968
    int tailRows = N - M0;             // 32
    int gemmGrid = 152;                // 1 CTA/SM (200.7KB smem)
    if (gemmGrid > fullTiles) gemmGrid = fullTiles;

    cudaMemsetAsync(d_out, 0, (size_t)N * F * sizeof(float));
    gemm_mma_kernel<<<gemmGrid, 256, GSMEM_BYTES>>>(x, w, fullTiles);
    if (tailRows > 0) gemm_tail_kernel<<<tailRows, 128>>>(x, w, M0, N);
    scatter_kernel<<<(E + 7) / 8, 256>>>(ei, out, E);
    postproc_kernel<<<(N + 7) / 8, 256>>>(out, bias, att, N);
    alpha_exp_kernel<<<(E + 255) / 256, 256>>>(ei, E);
    scale_kernel<<<(int)(((size_t)N * 32 + 255) / 256), 256>>>(out, bias, N);
}

// round 9
// speedup vs baseline: 1.5813x; 1.1494x over previous
#include <cuda_runtime.h>
#include <cuda_fp16.h>
#include <mma.h>
#include <cstdint>

using namespace nvcuda;

#define MAXN 500000
#define MAXE 500000
#define F 128

// ---------------- scratch (static device globals; no allocation) ----------------
__device__ __half g_h[(size_t)MAXN * F];    // h = x @ W (fp16)
__device__ __half g_acc[(size_t)MAXN * F];  // edge-sum accumulator (fp16)
__device__ float g_s[MAXN];                 // per-node dot with a_src
__device__ float g_d[MAXN];                 // per-node dot with a_dst
__device__ float g_alpha[MAXE];             // per-edge exp(logit)
__device__ float g_sum;                     // softmax denominator

// ---------------- small helpers ----------------
__device__ __forceinline__ float warpSum(float v) {
    #pragma unroll
    for (int o = 16; o > 0; o >>= 1) v += __shfl_xor_sync(0xFFFFFFFFu, v, o);
    return v;
}
__device__ __forceinline__ uint32_t smem_u32(const void* p) {
    uint32_t a;
    asm("{ .reg .u64 t; cvta.to.shared.u64 t, %1; cvt.u32.u64 %0, t; }" : "=r"(a) : "l"(p));
    return a;
}

// ---------------- K1: h = x @ W, persistent pipelined wmma-fp16 ----------------
// 256 threads, 8 warps = 4(M) x 2(N); warp tile 32x64 = 2x4 m16n16k16 frags.
// x staged fp32 via cp.async, converted to fp16 in SMEM each tile.
#define WH_LD 136
#define XH_LD 136
#define SW_HALFS   (128 * WH_LD)              // 17408
#define XF_FLOATS  (128 * 128)                // 16384
#define XH_HALFS   (128 * XH_LD)              // 17408
#define STG_FLOATS (8 * 32 * 64)              // 16384
#define GSMEM_BYTES (SW_HALFS * 2 + XF_FLOATS * 4 + XH_HALFS * 2 + STG_FLOATS * 4)

__device__ __forceinline__ void prefetch_tile32(const float* __restrict__ x, int tile,
                                                float* dst, int tid) {
    const float4* src = reinterpret_cast<const float4*>(x + (size_t)tile * 128 * F);
    #pragma unroll
    for (int i = 0; i < 16; i++) {
        int q = tid + i * 256;               // float4 id, 4096 total
        uint32_t d = smem_u32(dst + q * 4);
        asm volatile("cp.async.cg.shared.global [%0], [%1], 16;"
                     :: "r"(d), "l"(src + q) : "memory");
    }
    asm volatile("cp.async.commit_group;" ::: "memory");
}

__global__ __launch_bounds__(256) void gemm_mma_kernel(const float* __restrict__ x,
                                                       const float* __restrict__ w,
                                                       int numTiles) {
    extern __shared__ char smem_raw[];
    __half* sW  = reinterpret_cast<__half*>(smem_raw);
    float*  sXf = reinterpret_cast<float*>(smem_raw + SW_HALFS * 2);
    __half* sXh = reinterpret_cast<__half*>(smem_raw + SW_HALFS * 2 + XF_FLOATS * 4);
    float*  sStg = reinterpret_cast<float*>(smem_raw + SW_HALFS * 2 + XF_FLOATS * 4 + XH_HALFS * 2);
    const int tid = threadIdx.x;
    const int stride = gridDim.x;

    if (blockIdx.x == 0 && tid == 0) g_sum = 0.0f;

    // Stage W (K x N row-major) once as fp16.
    #pragma unroll
    for (int i = 0; i < 16; i++) {
        int q = tid + i * 256;       // float4 id, 4096 total
        int k = q >> 5;
        int c4 = q & 31;
        float4 v = reinterpret_cast<const float4*>(w)[q];
        __half2 p0 = __floats2half2_rn(v.x, v.y);
        __half2 p1 = __floats2half2_rn(v.z, v.w);
        *reinterpret_cast<__half2*>(&sW[k * WH_LD + c4 * 4])     = p0;
        *reinterpret_cast<__half2*>(&sW[k * WH_LD + c4 * 4 + 2]) = p1;
    }

    int t0 = blockIdx.x;
    if (t0 < numTiles) prefetch_tile32(x, t0, sXf, tid);

    const int wid = tid >> 5;
    const int lane = tid & 31;
    const int warp_m = wid & 3;          // 0..3
    const int warp_n = wid >> 2;         // 0..1
    const int n0 = warp_n * 64;
    float* myStg = sStg + wid * 2048;    // 32x64 fp32 per warp

    for (int t = t0; t < numTiles; t += stride) {
        asm volatile("cp.async.wait_group 0;" ::: "memory");
        __syncthreads();    // x fp32 tile ready; also covers W staging on first iter

        // Convert fp32 tile -> fp16 tile (padded ld).
        #pragma unroll
        for (int i = 0; i < 16; i++) {
            int q = tid + i * 256;       // float4 id
            int r = q >> 5;
            int c4 = q & 31;
            float4 v = *reinterpret_cast<const float4*>(&sXf[q * 4]);
            __half2 p0 = __floats2half2_rn(v.x, v.y);
            __half2 p1 = __floats2half2_rn(v.z, v.w);
            *reinterpret_cast<__half2*>(&sXh[r * XH_LD + c4 * 4])     = p0;
            *reinterpret_cast<__half2*>(&sXh[r * XH_LD + c4 * 4 + 2]) = p1;
        }
        __syncthreads();

        int tn = t + stride;
        if (tn < numTiles) prefetch_tile32(x, tn, sXf, tid);

        const __half* aBase = sXh + warp_m * 32 * XH_LD;

        wmma::fragment<wmma::accumulator, 16, 16, 16, float> c[2][4];
        #pragma unroll
        for (int mi = 0; mi < 2; mi++)
            #pragma unroll
            for (int ni = 0; ni < 4; ni++) wmma::fill_fragment(c[mi][ni], 0.0f);

        #pragma unroll
        for (int kf = 0; kf < 8; kf++) {
            const int k = kf * 16;
            wmma::fragment<wmma::matrix_a, 16, 16, 16, __half, wmma::row_major> a[2];
            wmma::fragment<wmma::matrix_b, 16, 16, 16, __half, wmma::row_major> b[4];
            #pragma unroll
            for (int mi = 0; mi < 2; mi++)
                wmma::load_matrix_sync(a[mi], aBase + mi * 16 * XH_LD + k, XH_LD);
            #pragma unroll
            for (int ni = 0; ni < 4; ni++)
                wmma::load_matrix_sync(b[ni], &sW[k * WH_LD + n0 + ni * 16], WH_LD);
            #pragma unroll
            for (int mi = 0; mi < 2; mi++)
                #pragma unroll
                for (int ni = 0; ni < 4; ni++)
                    wmma::mma_sync(c[mi][ni], a[mi], b[ni], c[mi][ni]);
        }

        // Epilogue: frags -> per-warp smem staging (fp32) -> fp16 global.
        #pragma unroll
        for (int mi = 0; mi < 2; mi++)
            #pragma unroll
            for (int ni = 0; ni < 4; ni++)
                wmma::store_matrix_sync(myStg + mi * 16 * 64 + ni * 16,
                                        c[mi][ni], 64, wmma::mem_row_major);
        __syncwarp();
        {
            const size_t m0 = (size_t)t * 128 + warp_m * 32;
            const float2* stg2 = reinterpret_cast<const float2*>(myStg);
            #pragma unroll 4
            for (int r = 0; r < 32; r++) {
                float2 v = stg2[r * 32 + lane];
                __half2 h2 = __floats2half2_rn(v.x, v.y);
                *reinterpret_cast<__half2*>(&g_h[(m0 + r) * F + n0 + lane * 2]) = h2;
            }
        }
        __syncwarp();
    }
}

// Tail rows [M0, N): one CTA per row, 128 threads (one per output col). fp32 math.
__global__ __launch_bounds__(128) void gemm_tail_kernel(const float* __restrict__ x,
                                                        const float* __restrict__ w,
                                                        int M0, int N) {
    __shared__ float sx[F];
    int r = M0 + blockIdx.x;
    if (r >= N) return;
    sx[threadIdx.x] = x[(size_t)r * F + threadIdx.x];
    __syncthreads();
    float acc = 0.f;
    #pragma unroll 8
    for (int k = 0; k < F; k++) acc = fmaf(sx[k], w[k * F + threadIdx.x], acc);
    g_h[(size_t)r * F + threadIdx.x] = __float2half_rn(acc);
}

// ---------------- K2: acc[row[e]] += h[col[e]]  (fp16 vector atomics) ----------------
__global__ __launch_bounds__(256) void scatter_kernel(const int* __restrict__ ei, int E) {
    int e = (blockIdx.x * blockDim.x + threadIdx.x) >> 5;
    int lane = threadIdx.x & 31;
    if (e >= E) return;
    int r = ei[e];
    int c = ei[E + e];
    uint2 pk = reinterpret_cast<const uint2*>(&g_h[(size_t)c * F])[lane];  // 4 halfs
    __half* dst = &g_acc[(size_t)r * F + lane * 4];
    asm volatile("red.global.add.noftz.v2.f16x2 [%0], {%1,%2};"
                 :: "l"(dst), "r"(pk.x), "r"(pk.y)
                 : "memory");
}

// ---------------- K3: s[i], d[i] from relu(acc+bias) — read fp16 acc ----------------
__global__ __launch_bounds__(256) void postproc_kernel(const float* __restrict__ bias,
                                                       const float* __restrict__ att,
                                                       int N) {
    int node = (blockIdx.x * blockDim.x + threadIdx.x) >> 5;
    int lane = threadIdx.x & 31;
    if (node >= N) return;
    uint2 pk = reinterpret_cast<const uint2*>(&g_acc[(size_t)node * F])[lane];
    float2 f0 = __half22float2(*reinterpret_cast<__half2*>(&pk.x));
    float2 f1 = __half22float2(*reinterpret_cast<__half2*>(&pk.y));
    float4 b = reinterpret_cast<const float4*>(bias)[lane];
    float4 v;
    v.x = fmaxf(f0.x + b.x, 0.f);
    v.y = fmaxf(f0.y + b.y, 0.f);
    v.z = fmaxf(f1.x + b.z, 0.f);
    v.w = fmaxf(f1.y + b.w, 0.f);
    float4 as = reinterpret_cast<const float4*>(att)[lane];       // a_src
    float4 ad = reinterpret_cast<const float4*>(att)[32 + lane];  // a_dst
    float ss = v.x * as.x + v.y * as.y + v.z * as.z + v.w * as.w;
    float dd = v.x * ad.x + v.y * ad.y + v.z * ad.z + v.w * ad.w;
    ss = warpSum(ss);
    dd = warpSum(dd);
    if (lane == 0) { g_s[node] = ss; g_d[node] = dd; }
}

// ---------------- K4: alpha[e]=exp(leaky_relu(s[row]+d[col])); global sum ----------
// Unstable softmax (no max subtraction): logits are small dot products, |logit| << 88,
// so exp cannot overflow; result is mathematically identical to max-shifted softmax.
__global__ __launch_bounds__(256) void alpha_exp_kernel(const int* __restrict__ ei, int E) {
    int e = blockIdx.x * blockDim.x + threadIdx.x;
    int lane = threadIdx.x & 31;
    int wid = threadIdx.x >> 5;
    float ev = 0.f;
    if (e < E) {
        int r = ei[e];
        int c = ei[E + e];
        float v = g_s[r] + g_d[c];
        v = (v > 0.f) ? v : 0.2f * v;
        ev = __expf(v);
        g_alpha[e] = ev;
    }
    __shared__ float ssum[8];
    float s = warpSum(ev);
    if (lane == 0) ssum[wid] = s;
    __syncthreads();
    if (wid == 0) {
        float t = (lane < 8) ? ssum[lane] : 0.f;
        t = warpSum(t);
        if (lane == 0) atomicAdd(&g_sum, t);
    }
}

// ---------------- K5: out[i,:] = relu(acc[i,:]+bias) * alpha[i]/sum ----------------
__global__ __launch_bounds__(256) void scale_kernel(float* __restrict__ out,
                                                    const float* __restrict__ bias,
                                                    int N) {
    size_t i = (size_t)blockIdx.x * blockDim.x + threadIdx.x;  // float4 index
    if (i >= (size_t)N * 32) return;
    int node = (int)(i >> 5);
    float sc = g_alpha[node] / g_sum;
    uint2 pk = reinterpret_cast<const uint2*>(g_acc)[i];
    float2 f0 = __half22float2(*reinterpret_cast<__half2*>(&pk.x));
    float2 f1 = __half22float2(*reinterpret_cast<__half2*>(&pk.y));
    float4 b = reinterpret_cast<const float4*>(bias)[i & 31];
    float4 v;
    v.x = fmaxf(f0.x + b.x, 0.f) * sc;
    v.y = fmaxf(f0.y + b.y, 0.f) * sc;
    v.z = fmaxf(f1.x + b.z, 0.f) * sc;
    v.w = fmaxf(f1.y + b.w, 0.f) * sc;
    reinterpret_cast<float4*>(out)[i] = v;
}

extern "C" void kernel_launch(void* const* d_in, const int* in_sizes, int n_in,
                              void* d_out, int out_size) {
    const float* x   = (const float*)d_in[0];
    const int* ei    = (const int*)d_in[1];     // edge_index: int32
    const float* w   = (const float*)d_in[2];
    const float* att = (const float*)d_in[3];
    const float* bias= (const float*)d_in[4];
    float* out       = (float*)d_out;

    int N = in_sizes[0] / F;   // 500000
    int E = in_sizes[1] / 2;   // 500000

    static void* acc_ptr = nullptr;
    if (!acc_ptr) {
        cudaFuncSetAttribute(gemm_mma_kernel, cudaFuncAttributeMaxDynamicSharedMemorySize, GSMEM_BYTES);
        cudaGetSymbolAddress(&acc_ptr, g_acc);
    }

    int fullTiles = N / 128;           // 3906
    int M0 = fullTiles * 128;          // 499968
    int tailRows = N - M0;             // 32
    int gemmGrid = 152;                // 1 CTA/SM (200.7KB smem)
    if (gemmGrid > fullTiles) gemmGrid = fullTiles;

    cudaMemsetAsync(acc_ptr, 0, (size_t)N * F * sizeof(__half));
    gemm_mma_kernel<<<gemmGrid, 256, GSMEM_BYTES>>>(x, w, fullTiles);
    if (tailRows > 0) gemm_tail_kernel<<<tailRows, 128>>>(x, w, M0, N);
    scatter_kernel<<<(E + 7) / 8, 256>>>(ei, E);
    postproc_kernel<<<(N + 7) / 8, 256>>>(bias, att, N);
    alpha_exp_kernel<<<(E + 255) / 256, 256>>>(ei, E);
    scale_kernel<<<(int)(((size_t)N * 32 + 255) / 256), 256>>>(out, bias, N);
}

// round 10
// speedup vs baseline: 1.6815x; 1.0633x over previous
#include <cuda_runtime.h>
#include <cuda_fp16.h>
#include <mma.h>
#include <cstdint>

using namespace nvcuda;

#define MAXN 500000
#define MAXE 500000
#define F 128

// ---------------- scratch (static device globals; no allocation) ----------------
__device__ __half g_h[(size_t)MAXN * F];    // h = x @ W (fp16)
__device__ __half g_acc[(size_t)MAXN * F];  // edge-sum accumulator (fp16)
__device__ float g_s[MAXN];                 // per-node dot with a_src
__device__ float g_d[MAXN];                 // per-node dot with a_dst
__device__ float g_alpha[MAXE];             // per-edge exp(logit)
__device__ float g_sum;                     // softmax denominator

// ---------------- small helpers ----------------
__device__ __forceinline__ float warpSum(float v) {
    #pragma unroll
    for (int o = 16; o > 0; o >>= 1) v += __shfl_xor_sync(0xFFFFFFFFu, v, o);
    return v;
}
__device__ __forceinline__ uint32_t smem_u32(const void* p) {
    uint32_t a;
    asm("{ .reg .u64 t; cvta.to.shared.u64 t, %1; cvt.u32.u64 %0, t; }" : "=r"(a) : "l"(p));
    return a;
}

// ---------------- K1: h = x @ W, persistent pipelined wmma-fp16 ----------------
// 256 threads, 8 warps = 4(M) x 2(N); warp tile 32x64 = 2x4 m16n16k16 frags.
// x staged fp32 via cp.async (double buffered), converted to fp16 in SMEM.
// Epilogue staging reuses sXh after the post-MMA barrier (two 16-row waves).
// SMEM: W 34816 | xf32 x2 131072 | xh16 34816 = 200704 bytes -> 1 CTA/SM.
#define WH_LD 136
#define XH_LD 136
#define SW_HALFS   (128 * WH_LD)              // 17408
#define XF_FLOATS  (128 * 128)                // 16384
#define XH_HALFS   (128 * XH_LD)              // 17408
#define GSMEM_BYTES (SW_HALFS * 2 + 2 * XF_FLOATS * 4 + XH_HALFS * 2)

__device__ __forceinline__ void prefetch_tile32(const float* __restrict__ x, int tile,
                                                float* dst, int tid) {
    const float4* src = reinterpret_cast<const float4*>(x + (size_t)tile * 128 * F);
    #pragma unroll
    for (int i = 0; i < 16; i++) {
        int q = tid + i * 256;               // float4 id, 4096 total
        uint32_t d = smem_u32(dst + q * 4);
        asm volatile("cp.async.cg.shared.global [%0], [%1], 16;"
                     :: "r"(d), "l"(src + q) : "memory");
    }
    asm volatile("cp.async.commit_group;" ::: "memory");
}

__global__ __launch_bounds__(256) void gemm_mma_kernel(const float* __restrict__ x,
                                                       const float* __restrict__ w,
                                                       int numTiles) {
    extern __shared__ char smem_raw[];
    __half* sW   = reinterpret_cast<__half*>(smem_raw);
    float*  sXf0 = reinterpret_cast<float*>(smem_raw + SW_HALFS * 2);
    float*  sXf1 = sXf0 + XF_FLOATS;
    __half* sXh  = reinterpret_cast<__half*>(smem_raw + SW_HALFS * 2 + 2 * XF_FLOATS * 4);
    const int tid = threadIdx.x;
    const int stride = gridDim.x;

    if (blockIdx.x == 0 && tid == 0) g_sum = 0.0f;

    // Stage W (K x N row-major) once as fp16.
    #pragma unroll
    for (int i = 0; i < 16; i++) {
        int q = tid + i * 256;       // float4 id, 4096 total
        int k = q >> 5;
        int c4 = q & 31;
        float4 v = reinterpret_cast<const float4*>(w)[q];
        __half2 p0 = __floats2half2_rn(v.x, v.y);
        __half2 p1 = __floats2half2_rn(v.z, v.w);
        *reinterpret_cast<__half2*>(&sW[k * WH_LD + c4 * 4])     = p0;
        *reinterpret_cast<__half2*>(&sW[k * WH_LD + c4 * 4 + 2]) = p1;
    }

    int t0 = blockIdx.x;
    if (t0 < numTiles) prefetch_tile32(x, t0, sXf0, tid);

    const int wid = tid >> 5;
    const int lane = tid & 31;
    const int warp_m = wid & 3;          // 0..3
    const int warp_n = wid >> 2;         // 0..1
    const int n0 = warp_n * 64;

    int buf = 0;
    for (int t = t0; t < numTiles; t += stride) {
        asm volatile("cp.async.wait_group 0;" ::: "memory");
        __syncthreads();    // current fp32 tile landed; also covers W staging / prior epilogue

        // Immediately start next tile's DMA into the other buffer (full overlap).
        int tn = t + stride;
        if (tn < numTiles) prefetch_tile32(x, tn, buf ? sXf0 : sXf1, tid);

        // Convert current fp32 tile -> fp16 tile (padded ld).
        const float* curF = buf ? sXf1 : sXf0;
        #pragma unroll
        for (int i = 0; i < 16; i++) {
            int q = tid + i * 256;       // float4 id
            int r = q >> 5;
            int c4 = q & 31;
            float4 v = *reinterpret_cast<const float4*>(&curF[q * 4]);
            __half2 p0 = __floats2half2_rn(v.x, v.y);
            __half2 p1 = __floats2half2_rn(v.z, v.w);
            *reinterpret_cast<__half2*>(&sXh[r * XH_LD + c4 * 4])     = p0;
            *reinterpret_cast<__half2*>(&sXh[r * XH_LD + c4 * 4 + 2]) = p1;
        }
        __syncthreads();

        const __half* aBase = sXh + warp_m * 32 * XH_LD;

        wmma::fragment<wmma::accumulator, 16, 16, 16, float> c[2][4];
        #pragma unroll
        for (int mi = 0; mi < 2; mi++)
            #pragma unroll
            for (int ni = 0; ni < 4; ni++) wmma::fill_fragment(c[mi][ni], 0.0f);

        #pragma unroll
        for (int kf = 0; kf < 8; kf++) {
            const int k = kf * 16;
            wmma::fragment<wmma::matrix_a, 16, 16, 16, __half, wmma::row_major> a[2];
            wmma::fragment<wmma::matrix_b, 16, 16, 16, __half, wmma::row_major> b[4];
            #pragma unroll
            for (int mi = 0; mi < 2; mi++)
                wmma::load_matrix_sync(a[mi], aBase + mi * 16 * XH_LD + k, XH_LD);
            #pragma unroll
            for (int ni = 0; ni < 4; ni++)
                wmma::load_matrix_sync(b[ni], &sW[k * WH_LD + n0 + ni * 16], WH_LD);
            #pragma unroll
            for (int mi = 0; mi < 2; mi++)
                #pragma unroll
                for (int ni = 0; ni < 4; ni++)
                    wmma::mma_sync(c[mi][ni], a[mi], b[ni], c[mi][ni]);
        }

        __syncthreads();   // all warps done reading sXh; safe to reuse as staging

        // Epilogue: two 16-row waves through sXh-as-fp32 staging -> fp16 global.
        float* myStg = reinterpret_cast<float*>(sXh) + wid * 1024;   // 16x64 fp32
        #pragma unroll
        for (int mi = 0; mi < 2; mi++) {
            #pragma unroll
            for (int ni = 0; ni < 4; ni++)
                wmma::store_matrix_sync(myStg + ni * 16, c[mi][ni], 64, wmma::mem_row_major);
            __syncwarp();
            const size_t m0 = (size_t)t * 128 + warp_m * 32 + mi * 16;
            const float2* stg2 = reinterpret_cast<const float2*>(myStg);
            #pragma unroll 4
            for (int r = 0; r < 16; r++) {
                float2 v = stg2[r * 32 + lane];
                __half2 h2 = __floats2half2_rn(v.x, v.y);
                *reinterpret_cast<__half2*>(&g_h[(m0 + r) * F + n0 + lane * 2]) = h2;
            }
            __syncwarp();
        }
        buf ^= 1;
    }
}

// Tail rows [M0, N): one CTA per row, 128 threads (one per output col). fp32 math.
__global__ __launch_bounds__(128) void gemm_tail_kernel(const float* __restrict__ x,
                                                        const float* __restrict__ w,
                                                        int M0, int N) {
    __shared__ float sx[F];
    int r = M0 + blockIdx.x;
    if (r >= N) return;
    sx[threadIdx.x] = x[(size_t)r * F + threadIdx.x];
    __syncthreads();
    float acc = 0.f;
    #pragma unroll 8
    for (int k = 0; k < F; k++) acc = fmaf(sx[k], w[k * F + threadIdx.x], acc);
    g_h[(size_t)r * F + threadIdx.x] = __float2half_rn(acc);
}

// ---------------- K2: acc[row[e]] += h[col[e]]  (fp16 vector atomics) ----------------
__global__ __launch_bounds__(256) void scatter_kernel(const int* __restrict__ ei, int E) {
    int e = (blockIdx.x * blockDim.x + threadIdx.x) >> 5;
    int lane = threadIdx.x & 31;
    if (e >= E) return;
    int r = ei[e];
    int c = ei[E + e];
    uint2 pk = reinterpret_cast<const uint2*>(&g_h[(size_t)c * F])[lane];  // 4 halfs
    __half* dst = &g_acc[(size_t)r * F + lane * 4];
    asm volatile("red.global.add.noftz.v2.f16x2 [%0], {%1,%2};"
                 :: "l"(dst), "r"(pk.x), "r"(pk.y)
                 : "memory");
}

// ---------------- K3: s[i], d[i] from relu(acc+bias) — 4 nodes per warp (ILP) -------
__global__ __launch_bounds__(256) void postproc_kernel(const float* __restrict__ bias,
                                                       const float* __restrict__ att,
                                                       int N) {
    int warp = (blockIdx.x * blockDim.x + threadIdx.x) >> 5;
    int lane = threadIdx.x & 31;
    int nb = warp * 4;
    if (nb >= N) return;
    float4 b  = reinterpret_cast<const float4*>(bias)[lane];
    float4 as = reinterpret_cast<const float4*>(att)[lane];       // a_src
    float4 ad = reinterpret_cast<const float4*>(att)[32 + lane];  // a_dst

    uint2 pk[4];
    #pragma unroll
    for (int j = 0; j < 4; j++) {
        int node = nb + j;
        pk[j] = (node < N) ? reinterpret_cast<const uint2*>(&g_acc[(size_t)node * F])[lane]
                           : make_uint2(0u, 0u);
    }
    float ss[4], dd[4];
    #pragma unroll
    for (int j = 0; j < 4; j++) {
        float2 f0 = __half22float2(*reinterpret_cast<__half2*>(&pk[j].x));
        float2 f1 = __half22float2(*reinterpret_cast<__half2*>(&pk[j].y));
        float vx = fmaxf(f0.x + b.x, 0.f);
        float vy = fmaxf(f0.y + b.y, 0.f);
        float vz = fmaxf(f1.x + b.z, 0.f);
        float vw = fmaxf(f1.y + b.w, 0.f);
        ss[j] = vx * as.x + vy * as.y + vz * as.z + vw * as.w;
        dd[j] = vx * ad.x + vy * ad.y + vz * ad.z + vw * ad.w;
    }
    #pragma unroll
    for (int o = 16; o > 0; o >>= 1) {
        #pragma unroll
        for (int j = 0; j < 4; j++) {
            ss[j] += __shfl_xor_sync(0xFFFFFFFFu, ss[j], o);
            dd[j] += __shfl_xor_sync(0xFFFFFFFFu, dd[j], o);
        }
    }
    if (lane == 0) {
        #pragma unroll
        for (int j = 0; j < 4; j++) {
            if (nb + j < N) { g_s[nb + j] = ss[j]; g_d[nb + j] = dd[j]; }
        }
    }
}

// ---------------- K4: alpha[e]=exp(leaky_relu(s[row]+d[col])); global sum ----------
// Unstable softmax (no max subtraction): logits are small dot products, |logit| << 88,
// so exp cannot overflow; result is mathematically identical to max-shifted softmax.
__global__ __launch_bounds__(256) void alpha_exp_kernel(const int* __restrict__ ei, int E) {
    int e = blockIdx.x * blockDim.x + threadIdx.x;
    int lane = threadIdx.x & 31;
    int wid = threadIdx.x >> 5;
    float ev = 0.f;
    if (e < E) {
        int r = ei[e];
        int c = ei[E + e];
        float v = g_s[r] + g_d[c];
        v = (v > 0.f) ? v : 0.2f * v;
        ev = __expf(v);
        g_alpha[e] = ev;
    }
    __shared__ float ssum[8];
    float s = warpSum(ev);
    if (lane == 0) ssum[wid] = s;
    __syncthreads();
    if (wid == 0) {
        float t = (lane < 8) ? ssum[lane] : 0.f;
        t = warpSum(t);
        if (lane == 0) atomicAdd(&g_sum, t);
    }
}

// ---------------- K5: out[i,:] = relu(acc[i,:]+bias) * alpha[i]/sum ----------------
__global__ __launch_bounds__(256) void scale_kernel(float* __restrict__ out,
                                                    const float* __restrict__ bias,
                                                    int N) {
    size_t i = (size_t)blockIdx.x * blockDim.x + threadIdx.x;  // float4 index
    if (i >= (size_t)N * 32) return;
    int node = (int)(i >> 5);
    float sc = g_alpha[node] / g_sum;
    uint2 pk = reinterpret_cast<const uint2*>(g_acc)[i];
    float2 f0 = __half22float2(*reinterpret_cast<__half2*>(&pk.x));
    float2 f1 = __half22float2(*reinterpret_cast<__half2*>(&pk.y));
    float4 b = reinterpret_cast<const float4*>(bias)[i & 31];
    float4 v;
    v.x = fmaxf(f0.x + b.x, 0.f) * sc;
    v.y = fmaxf(f0.y + b.y, 0.f) * sc;
    v.z = fmaxf(f1.x + b.z, 0.f) * sc;
    v.w = fmaxf(f1.y + b.w, 0.f) * sc;
    reinterpret_cast<float4*>(out)[i] = v;
}

extern "C" void kernel_launch(void* const* d_in, const int* in_sizes, int n_in,
                              void* d_out, int out_size) {
    const float* x   = (const float*)d_in[0];
    const int* ei    = (const int*)d_in[1];     // edge_index: int32
    const float* w   = (const float*)d_in[2];
    const float* att = (const float*)d_in[3];
    const float* bias= (const float*)d_in[4];
    float* out       = (float*)d_out;

    int N = in_sizes[0] / F;   // 500000
    int E = in_sizes[1] / 2;   // 500000

    static void* acc_ptr = nullptr;
    if (!acc_ptr) {
        cudaFuncSetAttribute(gemm_mma_kernel, cudaFuncAttributeMaxDynamicSharedMemorySize, GSMEM_BYTES);
        cudaGetSymbolAddress(&acc_ptr, g_acc);
    }

    int fullTiles = N / 128;           // 3906
    int M0 = fullTiles * 128;          // 499968
    int tailRows = N - M0;             // 32
    int gemmGrid = 152;                // 1 CTA/SM (200.7KB smem)
    if (gemmGrid > fullTiles) gemmGrid = fullTiles;

    cudaMemsetAsync(acc_ptr, 0, (size_t)N * F * sizeof(__half));
    gemm_mma_kernel<<<gemmGrid, 256, GSMEM_BYTES>>>(x, w, fullTiles);
    if (tailRows > 0) gemm_tail_kernel<<<tailRows, 128>>>(x, w, M0, N);
    scatter_kernel<<<(E + 7) / 8, 256>>>(ei, E);
    postproc_kernel<<<(int)(((size_t)N / 4 + 7) / 8 + 1), 256>>>(bias, att, N);
    alpha_exp_kernel<<<(E + 255) / 256, 256>>>(ei, E);
    scale_kernel<<<(int)(((size_t)N * 32 + 255) / 256), 256>>>(out, bias, N);
}

// round 11
// speedup vs baseline: 1.7419x; 1.0359x over previous
#include <cuda_runtime.h>
#include <cuda_fp16.h>
#include <mma.h>
#include <cstdint>

using namespace nvcuda;

#define MAXN 500000
#define MAXE 500000
#define F 128

// ---------------- scratch (static device globals; no allocation) ----------------
__device__ __half g_h[(size_t)MAXN * F];    // h = x @ W (fp16)
__device__ __half g_acc[(size_t)MAXN * F];  // edge-sum accumulator (fp16)
__device__ float g_s[MAXN];                 // per-node dot with a_src
__device__ float g_d[MAXN];                 // per-node dot with a_dst
__device__ float g_alpha[MAXE];             // per-edge exp(logit)
__device__ float g_sum;                     // softmax denominator

// ---------------- small helpers ----------------
__device__ __forceinline__ float warpSum(float v) {
    #pragma unroll
    for (int o = 16; o > 0; o >>= 1) v += __shfl_xor_sync(0xFFFFFFFFu, v, o);
    return v;
}

// ---------------- K1: h = x @ W, persistent wmma-fp16, 2 CTAs/SM ----------------
// 256 threads, 8 warps = 4(M) x 2(N); warp tile 32x64 = 2x4 m16n16k16 frags.
// x loaded via LDG.128 -> cvt -> STS fp16 (no cp.async staging); the co-resident
// CTA's MMA phase hides the load latency. Also zeroes g_acc (fire-and-forget).
// SMEM: W 34816 + xh 34816 = 69632 bytes -> 2 CTAs/SM.
#define WH_LD 136
#define XH_LD 136
#define SW_HALFS   (128 * WH_LD)              // 17408
#define XH_HALFS   (128 * XH_LD)              // 17408
#define GSMEM_BYTES (SW_HALFS * 2 + XH_HALFS * 2)

__global__ __launch_bounds__(256, 2) void gemm_mma_kernel(const float* __restrict__ x,
                                                          const float* __restrict__ w,
                                                          int numTiles, int N) {
    extern __shared__ char smem_raw[];
    __half* sW  = reinterpret_cast<__half*>(smem_raw);
    __half* sXh = reinterpret_cast<__half*>(smem_raw + SW_HALFS * 2);
    const int tid = threadIdx.x;
    const int stride = gridDim.x;

    if (blockIdx.x == 0 && tid == 0) g_sum = 0.0f;

    // Zero g_acc: fire-and-forget streaming stores, drain behind compute.
    {
        uint4* a4 = reinterpret_cast<uint4*>(g_acc);
        size_t total = (size_t)N * 16;   // uint4 units (8 halfs each)
        const uint4 z = make_uint4(0u, 0u, 0u, 0u);
        for (size_t i = (size_t)blockIdx.x * 256 + tid; i < total; i += (size_t)stride * 256)
            a4[i] = z;
    }

    // Stage W (K x N row-major) once as fp16.
    #pragma unroll
    for (int i = 0; i < 16; i++) {
        int q = tid + i * 256;       // float4 id, 4096 total
        int k = q >> 5;
        int c4 = q & 31;
        float4 v = reinterpret_cast<const float4*>(w)[q];
        __half2 p0 = __floats2half2_rn(v.x, v.y);
        __half2 p1 = __floats2half2_rn(v.z, v.w);
        uint2 u;
        u.x = *reinterpret_cast<uint32_t*>(&p0);
        u.y = *reinterpret_cast<uint32_t*>(&p1);
        *reinterpret_cast<uint2*>(&sW[k * WH_LD + c4 * 4]) = u;
    }

    const int wid = tid >> 5;
    const int lane = tid & 31;
    const int warp_m = wid & 3;          // 0..3
    const int warp_n = wid >> 2;         // 0..1
    const int n0 = warp_n * 64;

    for (int t = blockIdx.x; t < numTiles; t += stride) {
        __syncthreads();    // prior epilogue readers done; sXh reusable as input tile

        // Load x tile (fp32, coalesced LDG.128), convert, store fp16 to SMEM.
        const float4* src = reinterpret_cast<const float4*>(x + (size_t)t * 128 * F);
        #pragma unroll
        for (int i = 0; i < 16; i++) {
            int q = tid + i * 256;       // float4 id
            int r = q >> 5;
            int c4 = q & 31;
            float4 v = src[q];
            __half2 p0 = __floats2half2_rn(v.x, v.y);
            __half2 p1 = __floats2half2_rn(v.z, v.w);
            uint2 u;
            u.x = *reinterpret_cast<uint32_t*>(&p0);
            u.y = *reinterpret_cast<uint32_t*>(&p1);
            *reinterpret_cast<uint2*>(&sXh[r * XH_LD + c4 * 4]) = u;
        }
        __syncthreads();

        const __half* aBase = sXh + warp_m * 32 * XH_LD;

        wmma::fragment<wmma::accumulator, 16, 16, 16, float> c[2][4];
        #pragma unroll
        for (int mi = 0; mi < 2; mi++)
            #pragma unroll
            for (int ni = 0; ni < 4; ni++) wmma::fill_fragment(c[mi][ni], 0.0f);

        #pragma unroll
        for (int kf = 0; kf < 8; kf++) {
            const int k = kf * 16;
            wmma::fragment<wmma::matrix_a, 16, 16, 16, __half, wmma::row_major> a[2];
            wmma::fragment<wmma::matrix_b, 16, 16, 16, __half, wmma::row_major> b[4];
            #pragma unroll
            for (int mi = 0; mi < 2; mi++)
                wmma::load_matrix_sync(a[mi], aBase + mi * 16 * XH_LD + k, XH_LD);
            #pragma unroll
            for (int ni = 0; ni < 4; ni++)
                wmma::load_matrix_sync(b[ni], &sW[k * WH_LD + n0 + ni * 16], WH_LD);
            #pragma unroll
            for (int mi = 0; mi < 2; mi++)
                #pragma unroll
                for (int ni = 0; ni < 4; ni++)
                    wmma::mma_sync(c[mi][ni], a[mi], b[ni], c[mi][ni]);
        }

        __syncthreads();   // all warps done reading sXh; safe to reuse as staging

        // Epilogue: two 16-row waves through sXh-as-fp32 staging -> fp16 global.
        float* myStg = reinterpret_cast<float*>(sXh) + wid * 1024;   // 16x64 fp32
        #pragma unroll
        for (int mi = 0; mi < 2; mi++) {
            #pragma unroll
            for (int ni = 0; ni < 4; ni++)
                wmma::store_matrix_sync(myStg + ni * 16, c[mi][ni], 64, wmma::mem_row_major);
            __syncwarp();
            const size_t m0 = (size_t)t * 128 + warp_m * 32 + mi * 16;
            const float2* stg2 = reinterpret_cast<const float2*>(myStg);
            #pragma unroll 4
            for (int r = 0; r < 16; r++) {
                float2 v = stg2[r * 32 + lane];
                __half2 h2 = __floats2half2_rn(v.x, v.y);
                *reinterpret_cast<__half2*>(&g_h[(m0 + r) * F + n0 + lane * 2]) = h2;
            }
            __syncwarp();
        }
    }
}

// Tail rows [M0, N): one CTA per row, 128 threads (one per output col). fp32 math.
__global__ __launch_bounds__(128) void gemm_tail_kernel(const float* __restrict__ x,
                                                        const float* __restrict__ w,
                                                        int M0, int N) {
    __shared__ float sx[F];
    int r = M0 + blockIdx.x;
    if (r >= N) return;
    sx[threadIdx.x] = x[(size_t)r * F + threadIdx.x];
    __syncthreads();
    float acc = 0.f;
    #pragma unroll 8
    for (int k = 0; k < F; k++) acc = fmaf(sx[k], w[k * F + threadIdx.x], acc);
    g_h[(size_t)r * F + threadIdx.x] = __float2half_rn(acc);
}

// ---------------- K2: acc[row[e]] += h[col[e]]  (fp16 vector atomics) ----------------
__global__ __launch_bounds__(256) void scatter_kernel(const int* __restrict__ ei, int E) {
    int e = (blockIdx.x * blockDim.x + threadIdx.x) >> 5;
    int lane = threadIdx.x & 31;
    if (e >= E) return;
    int r = ei[e];
    int c = ei[E + e];
    uint2 pk = reinterpret_cast<const uint2*>(&g_h[(size_t)c * F])[lane];  // 4 halfs
    __half* dst = &g_acc[(size_t)r * F + lane * 4];
    asm volatile("red.global.add.noftz.v2.f16x2 [%0], {%1,%2};"
                 :: "l"(dst), "r"(pk.x), "r"(pk.y)
                 : "memory");
}

// ---------------- K3: s[i], d[i] from relu(acc+bias) — 4 nodes per warp (ILP) -------
__global__ __launch_bounds__(256) void postproc_kernel(const float* __restrict__ bias,
                                                       const float* __restrict__ att,
                                                       int N) {
    int warp = (blockIdx.x * blockDim.x + threadIdx.x) >> 5;
    int lane = threadIdx.x & 31;
    int nb = warp * 4;
    if (nb >= N) return;
    float4 b  = reinterpret_cast<const float4*>(bias)[lane];
    float4 as = reinterpret_cast<const float4*>(att)[lane];       // a_src
    float4 ad = reinterpret_cast<const float4*>(att)[32 + lane];  // a_dst

    uint2 pk[4];
    #pragma unroll
    for (int j = 0; j < 4; j++) {
        int node = nb + j;
        pk[j] = (node < N) ? reinterpret_cast<const uint2*>(&g_acc[(size_t)node * F])[lane]
                           : make_uint2(0u, 0u);
    }
    float ss[4], dd[4];
    #pragma unroll
    for (int j = 0; j < 4; j++) {
        float2 f0 = __half22float2(*reinterpret_cast<__half2*>(&pk[j].x));
        float2 f1 = __half22float2(*reinterpret_cast<__half2*>(&pk[j].y));
        float vx = fmaxf(f0.x + b.x, 0.f);
        float vy = fmaxf(f0.y + b.y, 0.f);
        float vz = fmaxf(f1.x + b.z, 0.f);
        float vw = fmaxf(f1.y + b.w, 0.f);
        ss[j] = vx * as.x + vy * as.y + vz * as.z + vw * as.w;
        dd[j] = vx * ad.x + vy * ad.y + vz * ad.z + vw * ad.w;
    }
    #pragma unroll
    for (int o = 16; o > 0; o >>= 1) {
        #pragma unroll
        for (int j = 0; j < 4; j++) {
            ss[j] += __shfl_xor_sync(0xFFFFFFFFu, ss[j], o);
            dd[j] += __shfl_xor_sync(0xFFFFFFFFu, dd[j], o);
        }
    }
    if (lane == 0) {
        #pragma unroll
        for (int j = 0; j < 4; j++) {
            if (nb + j < N) { g_s[nb + j] = ss[j]; g_d[nb + j] = dd[j]; }
        }
    }
}

// ---------------- K4: alpha[e]=exp(leaky_relu(s[row]+d[col])); global sum ----------
// Unstable softmax (no max subtraction): logits are small dot products, |logit| << 88,
// so exp cannot overflow; result is mathematically identical to max-shifted softmax.
__global__ __launch_bounds__(256) void alpha_exp_kernel(const int* __restrict__ ei, int E) {
    int e = blockIdx.x * blockDim.x + threadIdx.x;
    int lane = threadIdx.x & 31;
    int wid = threadIdx.x >> 5;
    float ev = 0.f;
    if (e < E) {
        int r = ei[e];
        int c = ei[E + e];
        float v = g_s[r] + g_d[c];
        v = (v > 0.f) ? v : 0.2f * v;
        ev = __expf(v);
        g_alpha[e] = ev;
    }
    __shared__ float ssum[8];
    float s = warpSum(ev);
    if (lane == 0) ssum[wid] = s;
    __syncthreads();
    if (wid == 0) {
        float t = (lane < 8) ? ssum[lane] : 0.f;
        t = warpSum(t);
        if (lane == 0) atomicAdd(&g_sum, t);
    }
}

// ---------------- K5: out[i,:] = relu(acc[i,:]+bias) * alpha[i]/sum ----------------
__global__ __launch_bounds__(256) void scale_kernel(float* __restrict__ out,
                                                    const float* __restrict__ bias,
                                                    int N) {
    size_t i = (size_t)blockIdx.x * blockDim.x + threadIdx.x;  // float4 index
    if (i >= (size_t)N * 32) return;
    int node = (int)(i >> 5);
    float sc = g_alpha[node] / g_sum;
    uint2 pk = reinterpret_cast<const uint2*>(g_acc)[i];
    float2 f0 = __half22float2(*reinterpret_cast<__half2*>(&pk.x));
    float2 f1 = __half22float2(*reinterpret_cast<__half2*>(&pk.y));
    float4 b = reinterpret_cast<const float4*>(bias)[i & 31];
    float4 v;
    v.x = fmaxf(f0.x + b.x, 0.f) * sc;
    v.y = fmaxf(f0.y + b.y, 0.f) * sc;
    v.z = fmaxf(f1.x + b.z, 0.f) * sc;
    v.w = fmaxf(f1.y + b.w, 0.f) * sc;
    reinterpret_cast<float4*>(out)[i] = v;
}

extern "C" void kernel_launch(void* const* d_in, const int* in_sizes, int n_in,
                              void* d_out, int out_size) {
    const float* x   = (const float*)d_in[0];
    const int* ei    = (const int*)d_in[1];     // edge_index: int32
    const float* w   = (const float*)d_in[2];
    const float* att = (const float*)d_in[3];
    const float* bias= (const float*)d_in[4];
    float* out       = (float*)d_out;

    int N = in_sizes[0] / F;   // 500000
    int E = in_sizes[1] / 2;   // 500000

    static int smem_set = 0;
    if (!smem_set) {
        cudaFuncSetAttribute(gemm_mma_kernel, cudaFuncAttributeMaxDynamicSharedMemorySize, GSMEM_BYTES);
        smem_set = 1;
    }

    int fullTiles = N / 128;           // 3906
    int M0 = fullTiles * 128;          // 499968
    int tailRows = N - M0;             // 32
    int gemmGrid = 304;                // 2 CTAs/SM on 152 SMs
    if (gemmGrid > fullTiles) gemmGrid = fullTiles;

    gemm_mma_kernel<<<gemmGrid, 256, GSMEM_BYTES>>>(x, w, fullTiles, N);
    if (tailRows > 0) gemm_tail_kernel<<<tailRows, 128>>>(x, w, M0, N);
    scatter_kernel<<<(E + 7) / 8, 256>>>(ei, E);
    postproc_kernel<<<(int)(((size_t)N / 4 + 7) / 8 + 1), 256>>>(bias, att, N);
    alpha_exp_kernel<<<(E + 255) / 256, 256>>>(ei, E);
    scale_kernel<<<(int)(((size_t)N * 32 + 255) / 256), 256>>>(out, bias, N);
}